// round 8
// baseline (speedup 1.0000x reference)
#include <cuda_runtime.h>
#include <math.h>

// Problem constants (fixed by the reference)
constexpr int Hc = 512, Wc = 512;
constexpr int Bc = 2, Gc = 4, Fc = 9, Cc = 3;
constexpr int Nn = Hc * Wc;

// Tiling
constexpr int TILE = 32;           // output tile
constexpr int RF   = TILE + 4;     // 36: fM + ew region (2-pixel halo), offset -2
constexpr int RD   = TILE + 2;     // 34: dinv/sig region (1-pixel halo), offset -1
constexpr int FSTR = 9;            // per-pixel stride for fM (9 coprime 32: conflict-free scalar LDS)
constexpr int NP   = RF * RF;      // 1296: ew plane size

constexpr int NTHREADS = 512;

// SMEM layout (floats).  sF is dead after phase 2a; SoA sig planes alias it.
constexpr int OFF_EW = 0;
constexpr int SZ_EW  = 5 * NP;               // 6480 (5 dir planes: self,E,SW,S,SE)
constexpr int OFF_U  = OFF_EW + SZ_EW;       // union region
constexpr int SZ_F   = NP * FSTR + 12;       // 11676 (pad: unconditional region-edge reads)
constexpr int SM_FLOATS = OFF_U + SZ_F;      // 18156
constexpr int SMEM_BYTES = SM_FLOATS * 4;    // 72624 B -> 3 blocks/SM

// Pair-packed multiM: per (g,f): pairs (c0,c1)(c2,c3)(c4,c5)(c6,c7)(c8,0)
__constant__ unsigned long long cMp[Gc * Fc * 5];
__device__   unsigned long long g_packM[Gc * Fc * 5];

__device__ __forceinline__ unsigned long long pk2(float lo, float hi) {
    unsigned long long r;
    asm("mov.b64 %0, {%1, %2};" : "=l"(r) : "f"(lo), "f"(hi));
    return r;
}
__device__ __forceinline__ void upk2(float& lo, float& hi, unsigned long long v) {
    asm("mov.b64 {%0, %1}, %2;" : "=f"(lo), "=f"(hi) : "l"(v));
}
__device__ __forceinline__ unsigned long long ffma2(unsigned long long a,
                                                    unsigned long long b,
                                                    unsigned long long c) {
    unsigned long long d;
    asm("fma.rn.f32x2 %0, %1, %2, %3;" : "=l"(d) : "l"(a), "l"(b), "l"(c));
    return d;
}
__device__ __forceinline__ unsigned long long fmul2(unsigned long long a,
                                                    unsigned long long b) {
    unsigned long long d;
    asm("mul.rn.f32x2 %0, %1, %2;" : "=l"(d) : "l"(a), "l"(b));
    return d;
}

__global__ void repack_kernel(const float* __restrict__ M) {
    int i = threadIdx.x;
    if (i < Gc * Fc * 5) {
        int g = i / 45, r = i % 45, f = r / 5, v = r % 5;
        float lo = M[g * 81 + f * 9 + 2 * v];
        float hi = (2 * v + 1 < 9) ? M[g * 81 + f * 9 + 2 * v + 1] : 0.f;
        g_packM[i] = pk2(lo, hi);
    }
}

__device__ __forceinline__ float dot9s(const float a[9], const float* __restrict__ q) {
    float s = a[0] * q[0];
    s = fmaf(a[1], q[1], s);
    s = fmaf(a[2], q[2], s);
    s = fmaf(a[3], q[3], s);
    s = fmaf(a[4], q[4], s);
    s = fmaf(a[5], q[5], s);
    s = fmaf(a[6], q[6], s);
    s = fmaf(a[7], q[7], s);
    s = fmaf(a[8], q[8], s);
    return s;
}

// Pure-FMA exp with clip to [-10,10]: no MUFU, no CVT.
// Range reduce via 1.5*2^23 rounding trick; Cephes degree-5 poly; IMAD exponent scale.
__device__ __forceinline__ float eclip(float x) {
    x = fminf(fmaxf(x, -10.f), 10.f);                 // NaN-safe: fmaxf(NaN,-10) = -10
    const float t = fmaf(x, 1.442695041f, 12582912.f); // x*log2e + 1.5*2^23
    const int   i = __float_as_int(t);                 // low bits hold round(x*log2e)
    const float j = t - 12582912.f;                    // = rint(x*log2e), |j| <= 15
    float f = fmaf(j, -0.693359375f, x);               // x - j*ln2_hi
    f = fmaf(j, 2.12194440e-4f, f);                    // - j*ln2_lo
    float p =        1.9875691500e-4f;
    p = fmaf(p, f,   1.3981999507e-3f);
    p = fmaf(p, f,   8.3334519073e-3f);
    p = fmaf(p, f,   4.1665795894e-2f);
    p = fmaf(p, f,   1.6666665459e-1f);
    p = fmaf(p, f,   5.0000001201e-1f);
    p = fmaf(f * f, p, f);                             // f + f^2*P(f)
    p += 1.0f;                                         // exp(f)
    const float s = __int_as_float((i + (127 - 0x4B400000)) << 23);  // 2^j
    return p * s;
}

// Packed-FMA feature transform (identical per-element fma order to scalar version).
// Writes the 9 fM floats to dst and returns the self-similarity dot (sum of squares).
__device__ __forceinline__ float compute_fm(const float* __restrict__ imgbg, int p,
                                            const unsigned long long* __restrict__ mp,
                                            float* __restrict__ dst) {
    unsigned long long a0 = 0ull, a1 = 0ull, a2 = 0ull, a3 = 0ull, a4 = 0ull;
    float ss = 0.f;
    #pragma unroll
    for (int f = 0; f < 9; f++) {
        const float x = __ldg(imgbg + (size_t)f * Nn + p);
        ss = fmaf(x, x, ss);
        const unsigned long long xx = pk2(x, x);
        a0 = ffma2(xx, mp[f * 5 + 0], a0);
        a1 = ffma2(xx, mp[f * 5 + 1], a1);
        a2 = ffma2(xx, mp[f * 5 + 2], a2);
        a3 = ffma2(xx, mp[f * 5 + 3], a3);
        a4 = ffma2(xx, mp[f * 5 + 4], a4);
    }
    const float inv = rsqrtf(fmaxf(ss, 1e-24f));
    const unsigned long long ii = pk2(inv, inv);
    float v0, v1, v2, v3, v4, v5, v6, v7, v8, hi;
    upk2(v0, v1, fmul2(a0, ii)); dst[0] = v0; dst[1] = v1;
    upk2(v2, v3, fmul2(a1, ii)); dst[2] = v2; dst[3] = v3;
    upk2(v4, v5, fmul2(a2, ii)); dst[4] = v4; dst[5] = v5;
    upk2(v6, v7, fmul2(a3, ii)); dst[6] = v6; dst[7] = v7;
    upk2(v8, hi, fmul2(a4, ii)); dst[8] = v8; (void)hi;
    float s = v0 * v0;
    s = fmaf(v1, v1, s); s = fmaf(v2, v2, s); s = fmaf(v3, v3, s);
    s = fmaf(v4, v4, s); s = fmaf(v5, v5, s); s = fmaf(v6, v6, s);
    s = fmaf(v7, v7, s); s = fmaf(v8, v8, s);
    return s;
}

__global__ void __launch_bounds__(NTHREADS, 3)
glr_fused_kernel(const float* __restrict__ img,
                 const float* __restrict__ sig,
                 float* __restrict__ out)
{
    extern __shared__ float sm[];
    float* __restrict__ sEw = sm + OFF_EW;   // 5 planes of NP
    float* __restrict__ sF  = sm + OFF_U;    // fM features (dead after phase 2a)
    float* __restrict__ sP0 = sm + OFF_U;                 // aliases sF
    float* __restrict__ sP1 = sm + OFF_U + RD * RD;
    float* __restrict__ sP2 = sm + OFF_U + 2 * RD * RD;
    float* __restrict__ sDv = sm + OFF_U + 3 * RD * RD;

    const int tid = threadIdx.x;
    const int bg  = blockIdx.z;
    const int g   = bg & (Gc - 1);
    const int x0  = blockIdx.x * TILE;
    const int y0  = blockIdx.y * TILE;
    const bool interior = (blockIdx.x >= 1) && (blockIdx.x <= 14) &&
                          (blockIdx.y >= 1) && (blockIdx.y <= 14);

    const float* __restrict__ imgbg = img + (size_t)bg * Fc * Nn;
    const float* __restrict__ sigbg = sig + (size_t)bg * Cc * Nn;
    const unsigned long long* __restrict__ mp = cMp + g * 45;

    // ------- Phase 1: fM over 36x36 region + self-similarity plane -------
    if (interior) {
        const int pbase = (y0 - 2) * Wc + (x0 - 2);
        for (int idx = tid; idx < NP; idx += NTHREADS) {
            const int ry = idx / RF;
            const int rx = idx - ry * RF;
            const float s = compute_fm(imgbg, pbase + ry * Wc + rx, mp, sF + idx * FSTR);
            sEw[idx] = eclip(s);
        }
    } else {
        for (int idx = tid; idx < NP; idx += NTHREADS) {
            const int ry = idx / RF;
            const int rx = idx - ry * RF;
            const int gy = y0 - 2 + ry;
            const int gx = x0 - 2 + rx;
            float* __restrict__ dst = sF + idx * FSTR;
            if ((unsigned)gy < (unsigned)Hc && (unsigned)gx < (unsigned)Wc) {
                const float s = compute_fm(imgbg, gy * Wc + gx, mp, dst);
                sEw[idx] = eclip(s);
            } else {
                #pragma unroll
                for (int v = 0; v < 9; v++) dst[v] = 0.f;
                sEw[idx] = 0.f;
            }
        }
    }
    __syncthreads();

    // ------- Phase 2a: 4-dir ew (E,SW,S,SE) over rows 0..34, plane layout -------
    if (interior) {
        // No predicates: region-edge out-of-window reads land in valid smem or the
        // 12-float pad; affected ew slots (E col35, SW col0, SE col35) never consumed.
        for (int idx = tid; idx < (RF - 1) * RF; idx += NTHREADS) {
            const float* __restrict__ pf = sF + idx * FSTR;
            float a[9];
            #pragma unroll
            for (int f = 0; f < 9; f++) a[f] = pf[f];
            sEw[NP + idx]     = eclip(dot9s(a, pf + FSTR));              // E
            sEw[2 * NP + idx] = eclip(dot9s(a, pf + (RF - 1) * FSTR));   // SW
            sEw[3 * NP + idx] = eclip(dot9s(a, pf + RF * FSTR));         // S
            sEw[4 * NP + idx] = eclip(dot9s(a, pf + (RF + 1) * FSTR));   // SE
        }
    } else {
        for (int idx = tid; idx < (RF - 1) * RF; idx += NTHREADS) {
            const int ry = idx / RF;
            const int rx = idx - ry * RF;
            const int gy = y0 - 2 + ry;
            const int gx = x0 - 2 + rx;
            if (((unsigned)gy < (unsigned)Hc) && ((unsigned)gx < (unsigned)Wc)) {
                const float* __restrict__ pf = sF + idx * FSTR;
                float a[9];
                #pragma unroll
                for (int f = 0; f < 9; f++) a[f] = pf[f];
                sEw[NP + idx] = (rx + 1 < RF && (unsigned)(gx + 1) < (unsigned)Wc)
                        ? eclip(dot9s(a, pf + FSTR)) : 0.f;
                sEw[2 * NP + idx] = (rx - 1 >= 0 &&
                         (unsigned)(gy + 1) < (unsigned)Hc && (unsigned)(gx - 1) < (unsigned)Wc)
                        ? eclip(dot9s(a, pf + (RF - 1) * FSTR)) : 0.f;
                sEw[3 * NP + idx] = ((unsigned)(gy + 1) < (unsigned)Hc)
                        ? eclip(dot9s(a, pf + RF * FSTR)) : 0.f;
                sEw[4 * NP + idx] = (rx + 1 < RF &&
                         (unsigned)(gy + 1) < (unsigned)Hc && (unsigned)(gx + 1) < (unsigned)Wc)
                        ? eclip(dot9s(a, pf + (RF + 1) * FSTR)) : 0.f;
            } else {
                sEw[NP + idx] = 0.f; sEw[2 * NP + idx] = 0.f;
                sEw[3 * NP + idx] = 0.f; sEw[4 * NP + idx] = 0.f;
            }
        }
    }
    __syncthreads();

    // ------- Phase 2b: deg -> dinv gather + prescaled sig (SoA), over 34x34 -------
    if (interior) {
        const int pbase = (y0 - 1) * Wc + (x0 - 1);
        for (int idx = tid; idx < RD * RD; idx += NTHREADS) {
            const int ly = idx / RD;
            const int lx = idx - ly * RD;
            const int r = (ly + 1) * RF + (lx + 1);
            float deg = sEw[r] + sEw[NP + r] + sEw[2 * NP + r] + sEw[3 * NP + r] + sEw[4 * NP + r];
            deg += sEw[4 * NP + r - RF - 1];  // NW = SE of up-left
            deg += sEw[3 * NP + r - RF];      // N  = S  of up
            deg += sEw[2 * NP + r - RF + 1];  // NE = SW of up-right
            deg += sEw[NP + r - 1];           // W  = E  of left
            const float dinv = rsqrtf(deg);   // deg >= 1
            const int p = pbase + ly * Wc + lx;
            sP0[idx] = __ldg(sigbg + p) * dinv;
            sP1[idx] = __ldg(sigbg + Nn + p) * dinv;
            sP2[idx] = __ldg(sigbg + 2 * Nn + p) * dinv;
            sDv[idx] = dinv;
        }
    } else {
        for (int idx = tid; idx < RD * RD; idx += NTHREADS) {
            const int ly = idx / RD;
            const int lx = idx - ly * RD;
            const int gy = y0 - 1 + ly;
            const int gx = x0 - 1 + lx;
            const bool inb = ((unsigned)gy < (unsigned)Hc) && ((unsigned)gx < (unsigned)Wc);
            const int r = (ly + 1) * RF + (lx + 1);
            float dinv = 0.f;
            if (inb) {
                float deg = sEw[r] + sEw[NP + r] + sEw[2 * NP + r] + sEw[3 * NP + r] + sEw[4 * NP + r];
                deg += sEw[4 * NP + r - RF - 1];
                deg += sEw[3 * NP + r - RF];
                deg += sEw[2 * NP + r - RF + 1];
                deg += sEw[NP + r - 1];
                dinv = rsqrtf(deg);
            }
            const int p = gy * Wc + gx;
            sP0[idx] = inb ? __ldg(sigbg + p) * dinv          : 0.f;
            sP1[idx] = inb ? __ldg(sigbg + Nn + p) * dinv     : 0.f;
            sP2[idx] = inb ? __ldg(sigbg + 2 * Nn + p) * dinv : 0.f;
            sDv[idx] = dinv;
        }
    }
    __syncthreads();

    // ---------------- Phase 3: aggregation + output (scalar fma) ----------------
    float* __restrict__ outbg = out + (size_t)bg * Cc * Nn;
    for (int idx = tid; idx < TILE * TILE; idx += NTHREADS) {
        const int ly = idx >> 5;
        const int lx = idx & 31;
        const int r = (ly + 2) * RF + (lx + 2);   // region coords
        const int d = (ly + 1) * RD + (lx + 1);   // RD coords

        const float dp = sDv[d];
        float S0 = 0.f, S1 = 0.f, S2 = 0.f;

        #define GLR_ACC(nn, ww) do {                \
            const float _w = (ww);                  \
            const int _n = (nn);                    \
            S0 = fmaf(sP0[_n], _w, S0);             \
            S1 = fmaf(sP1[_n], _w, S1);             \
            S2 = fmaf(sP2[_n], _w, S2);             \
        } while (0)

        GLR_ACC(d - RD - 1, sEw[4 * NP + r - RF - 1]);  // NW
        GLR_ACC(d - RD,     sEw[3 * NP + r - RF]);      // N
        GLR_ACC(d - RD + 1, sEw[2 * NP + r - RF + 1]);  // NE
        GLR_ACC(d - 1,      sEw[NP + r - 1]);           // W
        const float c0 = sP0[d], c1 = sP1[d], c2 = sP2[d];
        {
            const float w = sEw[r];                     // self
            S0 = fmaf(c0, w, S0); S1 = fmaf(c1, w, S1); S2 = fmaf(c2, w, S2);
        }
        GLR_ACC(d + 1,      sEw[NP + r]);               // E
        GLR_ACC(d + RD - 1, sEw[2 * NP + r]);           // SW
        GLR_ACC(d + RD,     sEw[3 * NP + r]);           // S
        GLR_ACC(d + RD + 1, sEw[4 * NP + r]);           // SE
        #undef GLR_ACC

        const float inv = __fdividef(1.0f, dp);         // dp in (0,1], MUFU.RCP
        const int p = (y0 + ly) * Wc + (x0 + lx);
        outbg[p]          = fmaf(-dp, S0, c0 * inv);
        outbg[Nn + p]     = fmaf(-dp, S1, c1 * inv);
        outbg[2 * Nn + p] = fmaf(-dp, S2, c2 * inv);
    }
}

extern "C" void kernel_launch(void* const* d_in, const int* in_sizes, int n_in,
                              void* d_out, int out_size) {
    const float* img = (const float*)d_in[0];  // (B,G,F,H,W)
    const float* sig = (const float*)d_in[1];  // (B,G,C,H,W)
    const float* M   = (const float*)d_in[2];  // (G,F,F)
    float* out = (float*)d_out;

    cudaFuncSetAttribute(glr_fused_kernel,
                         cudaFuncAttributeMaxDynamicSharedMemorySize, SMEM_BYTES);

    repack_kernel<<<1, 192>>>(M);
    void* packed_ptr = nullptr;
    cudaGetSymbolAddress(&packed_ptr, g_packM);
    cudaMemcpyToSymbolAsync(cMp, packed_ptr, Gc * Fc * 5 * sizeof(unsigned long long),
                            0, cudaMemcpyDeviceToDevice, 0);

    dim3 grid(Wc / TILE, Hc / TILE, Bc * Gc);
    glr_fused_kernel<<<grid, NTHREADS, SMEM_BYTES>>>(img, sig, out);
}

// round 9
// speedup vs baseline: 1.0266x; 1.0266x over previous
#include <cuda_runtime.h>
#include <math.h>

typedef unsigned long long u64;

// Problem constants (fixed by the reference)
constexpr int Hc = 512, Wc = 512;
constexpr int Bc = 2, Gc = 4, Fc = 9, Cc = 3;
constexpr int Nn = Hc * Wc;

// Tiling
constexpr int TILE = 32;           // output tile
constexpr int RF   = TILE + 4;     // 36: fM + ew region (2-pixel halo), offset -2
constexpr int RD   = TILE + 2;     // 34: dinv/sig region (1-pixel halo), offset -1
constexpr int NP   = RF * RF;      // 1296: fM plane size
constexpr int NP2  = (RF - 1) * RF;// 1260: ew plane size (row 35 never consumed)
constexpr int ND   = RD * RD;      // 1156

constexpr int NTHREADS = 512;

// SMEM layout (floats). fM pair-planes are dead after phase 2a; sig planes alias them.
constexpr int OFF_EW = 0;
constexpr int SZ_EW  = 5 * NP2;              // 6300 (self,E,SW,S,SE planes, stride NP2)
constexpr int OFF_U  = OFF_EW + SZ_EW;       // 6300 floats (byte 25200, 8B aligned)
// fM union layout (floats, relative to sm):
constexpr int FA = OFF_U;                    // u64 plane: (v0,v1)  NP entries
constexpr int FB = OFF_U + 2 * NP;           // u64 plane: (v2,v3)
constexpr int FC = OFF_U + 4 * NP;           // u64 plane: (v4,v5)
constexpr int FD = OFF_U + 6 * NP;           // u64 plane: (v6,v7)
constexpr int FE = OFF_U + 8 * NP;           // f32 plane: v8, NP + 40 pad
constexpr int SM_FLOATS = OFF_U + 9 * NP + 40;   // 18004
constexpr int SMEM_BYTES = SM_FLOATS * 4;        // 72016 B -> 3 blocks/SM

// Pair-packed multiM: per (g,f): pairs (c0,c1)(c2,c3)(c4,c5)(c6,c7)(c8,0)
__constant__ u64 cMp[Gc * Fc * 5];
__device__   u64 g_packM[Gc * Fc * 5];

__device__ __forceinline__ u64 pk2(float lo, float hi) {
    u64 r; asm("mov.b64 %0, {%1, %2};" : "=l"(r) : "f"(lo), "f"(hi)); return r;
}
__device__ __forceinline__ void upk2(float& lo, float& hi, u64 v) {
    asm("mov.b64 {%0, %1}, %2;" : "=f"(lo), "=f"(hi) : "l"(v));
}
__device__ __forceinline__ u64 ffma2(u64 a, u64 b, u64 c) {
    u64 d; asm("fma.rn.f32x2 %0, %1, %2, %3;" : "=l"(d) : "l"(a), "l"(b), "l"(c)); return d;
}
__device__ __forceinline__ u64 fmul2(u64 a, u64 b) {
    u64 d; asm("mul.rn.f32x2 %0, %1, %2;" : "=l"(d) : "l"(a), "l"(b)); return d;
}

__global__ void repack_kernel(const float* __restrict__ M) {
    int i = threadIdx.x;
    if (i < Gc * Fc * 5) {
        int g = i / 45, r = i % 45, f = r / 5, v = r % 5;
        float lo = M[g * 81 + f * 9 + 2 * v];
        float hi = (2 * v + 1 < 9) ? M[g * 81 + f * 9 + 2 * v + 1] : 0.f;
        g_packM[i] = pk2(lo, hi);
    }
}

__device__ __forceinline__ float eclip(float s) {
    // NaN-safe: fmaxf(NaN,-10) = -10
    return __expf(fminf(fmaxf(s, -10.f), 10.f));
}

// Packed feature transform: loads 9 img floats at p, normalizes, applies M.
// Writes pair-planes at index idx; returns self-similarity dot.
__device__ __forceinline__ float compute_fm(const float* __restrict__ imgbg, int p,
                                            const u64* __restrict__ mp,
                                            u64* sA, u64* sB, u64* sC, u64* sD,
                                            float* sE, int idx) {
    u64 a0 = 0ull, a1 = 0ull, a2 = 0ull, a3 = 0ull, a4 = 0ull;
    float ss = 0.f;
    #pragma unroll
    for (int f = 0; f < 9; f++) {
        const float x = __ldg(imgbg + (size_t)f * Nn + p);
        ss = fmaf(x, x, ss);
        const u64 xx = pk2(x, x);
        a0 = ffma2(xx, mp[f * 5 + 0], a0);
        a1 = ffma2(xx, mp[f * 5 + 1], a1);
        a2 = ffma2(xx, mp[f * 5 + 2], a2);
        a3 = ffma2(xx, mp[f * 5 + 3], a3);
        a4 = ffma2(xx, mp[f * 5 + 4], a4);
    }
    const float inv = rsqrtf(fmaxf(ss, 1e-24f));
    const u64 ii = pk2(inv, inv);
    const u64 r0 = fmul2(a0, ii), r1 = fmul2(a1, ii), r2 = fmul2(a2, ii),
              r3 = fmul2(a3, ii), r4 = fmul2(a4, ii);   // r4 hi lane = 0
    sA[idx] = r0; sB[idx] = r1; sC[idx] = r2; sD[idx] = r3;
    float v8, h; upk2(v8, h, r4); (void)h;
    sE[idx] = v8;
    // self-dot: pairs (hi lane of r4 is 0, harmless)
    u64 sd = fmul2(r0, r0);
    sd = ffma2(r1, r1, sd); sd = ffma2(r2, r2, sd);
    sd = ffma2(r3, r3, sd); sd = ffma2(r4, r4, sd);
    float lo, hi2; upk2(lo, hi2, sd);
    return lo + hi2;
}

// Scalar vector fetch from pair planes (boundary path)
__device__ __forceinline__ void load_vec(const u64* sA, const u64* sB, const u64* sC,
                                         const u64* sD, const float* sE, int idx,
                                         float a[9]) {
    upk2(a[0], a[1], sA[idx]);
    upk2(a[2], a[3], sB[idx]);
    upk2(a[4], a[5], sC[idx]);
    upk2(a[6], a[7], sD[idx]);
    a[8] = sE[idx];
}

__device__ __forceinline__ float dot9s(const float a[9], const float b[9]) {
    float s = a[0] * b[0];
    #pragma unroll
    for (int f = 1; f < 9; f++) s = fmaf(a[f], b[f], s);
    return s;
}

__global__ void __launch_bounds__(NTHREADS, 3)
glr_fused_kernel(const float* __restrict__ img,
                 const float* __restrict__ sig,
                 float* __restrict__ out)
{
    extern __shared__ float sm[];
    float* __restrict__ sEw = sm + OFF_EW;           // 5 planes, stride NP2
    u64*   __restrict__ sA  = reinterpret_cast<u64*>(sm + FA);
    u64*   __restrict__ sB  = reinterpret_cast<u64*>(sm + FB);
    u64*   __restrict__ sC  = reinterpret_cast<u64*>(sm + FC);
    u64*   __restrict__ sD  = reinterpret_cast<u64*>(sm + FD);
    float* __restrict__ sE  = sm + FE;
    // sig planes alias the fM union (fM dead after phase 2a)
    u64*   __restrict__ sP01 = reinterpret_cast<u64*>(sm + OFF_U);  // (s0',s1') ND entries
    float* __restrict__ sP2  = sm + OFF_U + 2 * ND;
    float* __restrict__ sDv  = sm + OFF_U + 3 * ND;

    const int tid = threadIdx.x;
    const int bg  = blockIdx.z;
    const int g   = bg & (Gc - 1);
    const int x0  = blockIdx.x * TILE;
    const int y0  = blockIdx.y * TILE;
    const bool interior = (blockIdx.x >= 1) && (blockIdx.x <= 14) &&
                          (blockIdx.y >= 1) && (blockIdx.y <= 14);

    const float* __restrict__ imgbg = img + (size_t)bg * Fc * Nn;
    const float* __restrict__ sigbg = sig + (size_t)bg * Cc * Nn;
    const u64* __restrict__ mp = cMp + g * 45;

    // ------- Phase 1: fM pair-planes over 36x36 + self-similarity plane -------
    if (interior) {
        const int pbase = (y0 - 2) * Wc + (x0 - 2);
        for (int idx = tid; idx < NP; idx += NTHREADS) {
            const int ry = idx / RF;
            const int rx = idx - ry * RF;
            const float s = compute_fm(imgbg, pbase + ry * Wc + rx, mp,
                                       sA, sB, sC, sD, sE, idx);
            if (idx < NP2) sEw[idx] = eclip(s);   // row 35 self never consumed
        }
    } else {
        for (int idx = tid; idx < NP; idx += NTHREADS) {
            const int ry = idx / RF;
            const int rx = idx - ry * RF;
            const int gy = y0 - 2 + ry;
            const int gx = x0 - 2 + rx;
            if ((unsigned)gy < (unsigned)Hc && (unsigned)gx < (unsigned)Wc) {
                const float s = compute_fm(imgbg, gy * Wc + gx, mp,
                                           sA, sB, sC, sD, sE, idx);
                if (idx < NP2) sEw[idx] = eclip(s);
            } else {
                sA[idx] = 0ull; sB[idx] = 0ull; sC[idx] = 0ull; sD[idx] = 0ull;
                sE[idx] = 0.f;
                if (idx < NP2) sEw[idx] = 0.f;
            }
        }
    }
    __syncthreads();

    // ------- Phase 2a: 4-dir ew (E,SW,S,SE) over rows 0..34, paired dots -------
    if (interior) {
        // Unpredicated: region-edge out-of-window reads land in valid smem / pad.
        // Affected ew slots (E col>=34 partly, SW col0, SE col35) are never consumed
        // or correspond to valid in-image pixels for interior blocks.
        for (int idx = tid; idx < NP2; idx += NTHREADS) {
            const u64 a01 = sA[idx], a23 = sB[idx], a45 = sC[idx], a67 = sD[idx];
            const float a8 = sE[idx];
            #pragma unroll
            for (int t = 0; t < 4; t++) {
                const int o = (t == 0) ? 1 : (t == 1) ? (RF - 1) : (t == 2) ? RF : (RF + 1);
                const int j = idx + o;
                u64 acc = fmul2(a01, sA[j]);
                acc = ffma2(a23, sB[j], acc);
                acc = ffma2(a45, sC[j], acc);
                acc = ffma2(a67, sD[j], acc);
                float lo, hi; upk2(lo, hi, acc);
                float s = fmaf(a8, sE[j], lo + hi);
                sEw[(t + 1) * NP2 + idx] = eclip(s);
            }
        }
    } else {
        for (int idx = tid; idx < NP2; idx += NTHREADS) {
            const int ry = idx / RF;
            const int rx = idx - ry * RF;
            const int gy = y0 - 2 + ry;
            const int gx = x0 - 2 + rx;
            if (((unsigned)gy < (unsigned)Hc) && ((unsigned)gx < (unsigned)Wc)) {
                float a[9], b[9];
                load_vec(sA, sB, sC, sD, sE, idx, a);
                float e1 = 0.f, e2 = 0.f, e3 = 0.f, e4 = 0.f;
                if (rx + 1 < RF && (unsigned)(gx + 1) < (unsigned)Wc) {
                    load_vec(sA, sB, sC, sD, sE, idx + 1, b);
                    e1 = eclip(dot9s(a, b));
                }
                if (rx - 1 >= 0 && (unsigned)(gy + 1) < (unsigned)Hc &&
                    (unsigned)(gx - 1) < (unsigned)Wc) {
                    load_vec(sA, sB, sC, sD, sE, idx + RF - 1, b);
                    e2 = eclip(dot9s(a, b));
                }
                if ((unsigned)(gy + 1) < (unsigned)Hc) {
                    load_vec(sA, sB, sC, sD, sE, idx + RF, b);
                    e3 = eclip(dot9s(a, b));
                }
                if (rx + 1 < RF && (unsigned)(gy + 1) < (unsigned)Hc &&
                    (unsigned)(gx + 1) < (unsigned)Wc) {
                    load_vec(sA, sB, sC, sD, sE, idx + RF + 1, b);
                    e4 = eclip(dot9s(a, b));
                }
                sEw[NP2 + idx] = e1; sEw[2 * NP2 + idx] = e2;
                sEw[3 * NP2 + idx] = e3; sEw[4 * NP2 + idx] = e4;
            } else {
                sEw[NP2 + idx] = 0.f; sEw[2 * NP2 + idx] = 0.f;
                sEw[3 * NP2 + idx] = 0.f; sEw[4 * NP2 + idx] = 0.f;
            }
        }
    }
    __syncthreads();

    // ------- Phase 2b: deg -> dinv gather + prescaled paired sig, over 34x34 -------
    if (interior) {
        const int pbase = (y0 - 1) * Wc + (x0 - 1);
        for (int idx = tid; idx < ND; idx += NTHREADS) {
            const int ly = idx / RD;
            const int lx = idx - ly * RD;
            const int r = (ly + 1) * RF + (lx + 1);
            float deg = sEw[r] + sEw[NP2 + r] + sEw[2 * NP2 + r]
                      + sEw[3 * NP2 + r] + sEw[4 * NP2 + r];
            deg += sEw[4 * NP2 + r - RF - 1];  // NW = SE of up-left
            deg += sEw[3 * NP2 + r - RF];      // N  = S  of up
            deg += sEw[2 * NP2 + r - RF + 1];  // NE = SW of up-right
            deg += sEw[NP2 + r - 1];           // W  = E  of left
            const float dinv = rsqrtf(deg);    // deg >= 1
            const int p = pbase + ly * Wc + lx;
            sP01[idx] = pk2(__ldg(sigbg + p) * dinv, __ldg(sigbg + Nn + p) * dinv);
            sP2[idx]  = __ldg(sigbg + 2 * Nn + p) * dinv;
            sDv[idx]  = dinv;
        }
    } else {
        for (int idx = tid; idx < ND; idx += NTHREADS) {
            const int ly = idx / RD;
            const int lx = idx - ly * RD;
            const int gy = y0 - 1 + ly;
            const int gx = x0 - 1 + lx;
            const bool inb = ((unsigned)gy < (unsigned)Hc) && ((unsigned)gx < (unsigned)Wc);
            const int r = (ly + 1) * RF + (lx + 1);
            float dinv = 0.f;
            if (inb) {
                float deg = sEw[r] + sEw[NP2 + r] + sEw[2 * NP2 + r]
                          + sEw[3 * NP2 + r] + sEw[4 * NP2 + r];
                deg += sEw[4 * NP2 + r - RF - 1];
                deg += sEw[3 * NP2 + r - RF];
                deg += sEw[2 * NP2 + r - RF + 1];
                deg += sEw[NP2 + r - 1];
                dinv = rsqrtf(deg);
            }
            const int p = gy * Wc + gx;
            const float s0 = inb ? __ldg(sigbg + p) * dinv          : 0.f;
            const float s1 = inb ? __ldg(sigbg + Nn + p) * dinv     : 0.f;
            const float s2 = inb ? __ldg(sigbg + 2 * Nn + p) * dinv : 0.f;
            sP01[idx] = pk2(s0, s1);
            sP2[idx]  = s2;
            sDv[idx]  = dinv;
        }
    }
    __syncthreads();

    // ---------------- Phase 3: aggregation + output ----------------
    // out_c = s'_c/dp - dp * S_c,  S_c = sum_t ew_t * s'_{c,nb(t)}
    float* __restrict__ outbg = out + (size_t)bg * Cc * Nn;
    for (int idx = tid; idx < TILE * TILE; idx += NTHREADS) {
        const int ly = idx >> 5;
        const int lx = idx & 31;
        const int r = (ly + 2) * RF + (lx + 2);   // region coords
        const int d = (ly + 1) * RD + (lx + 1);   // RD coords

        const float dp = sDv[d];
        u64 S01 = 0ull;
        float S2 = 0.f;

        #define GLR_ACC(nn, ww) do {                     \
            const float _w = (ww);                       \
            const int _n = (nn);                         \
            S01 = ffma2(sP01[_n], pk2(_w, _w), S01);     \
            S2  = fmaf(sP2[_n], _w, S2);                 \
        } while (0)

        GLR_ACC(d - RD - 1, sEw[4 * NP2 + r - RF - 1]);  // NW
        GLR_ACC(d - RD,     sEw[3 * NP2 + r - RF]);      // N
        GLR_ACC(d - RD + 1, sEw[2 * NP2 + r - RF + 1]);  // NE
        GLR_ACC(d - 1,      sEw[NP2 + r - 1]);           // W
        const u64 c01 = sP01[d];
        const float c2 = sP2[d];
        {
            const float w = sEw[r];                      // self
            S01 = ffma2(c01, pk2(w, w), S01);
            S2  = fmaf(c2, w, S2);
        }
        GLR_ACC(d + 1,      sEw[NP2 + r]);               // E
        GLR_ACC(d + RD - 1, sEw[2 * NP2 + r]);           // SW
        GLR_ACC(d + RD,     sEw[3 * NP2 + r]);           // S
        GLR_ACC(d + RD + 1, sEw[4 * NP2 + r]);           // SE
        #undef GLR_ACC

        float S0, S1; upk2(S0, S1, S01);
        float c0, c1; upk2(c0, c1, c01);
        const float inv = __fdividef(1.0f, dp);          // dp in (0,1]
        const int p = (y0 + ly) * Wc + (x0 + lx);
        outbg[p]          = fmaf(-dp, S0, c0 * inv);
        outbg[Nn + p]     = fmaf(-dp, S1, c1 * inv);
        outbg[2 * Nn + p] = fmaf(-dp, S2, c2 * inv);
    }
}

extern "C" void kernel_launch(void* const* d_in, const int* in_sizes, int n_in,
                              void* d_out, int out_size) {
    const float* img = (const float*)d_in[0];  // (B,G,F,H,W)
    const float* sig = (const float*)d_in[1];  // (B,G,C,H,W)
    const float* M   = (const float*)d_in[2];  // (G,F,F)
    float* out = (float*)d_out;

    cudaFuncSetAttribute(glr_fused_kernel,
                         cudaFuncAttributeMaxDynamicSharedMemorySize, SMEM_BYTES);

    repack_kernel<<<1, 192>>>(M);
    void* packed_ptr = nullptr;
    cudaGetSymbolAddress(&packed_ptr, g_packM);
    cudaMemcpyToSymbolAsync(cMp, packed_ptr, Gc * Fc * 5 * sizeof(u64),
                            0, cudaMemcpyDeviceToDevice, 0);

    dim3 grid(Wc / TILE, Hc / TILE, Bc * Gc);
    glr_fused_kernel<<<grid, NTHREADS, SMEM_BYTES>>>(img, sig, out);
}